// round 1
// baseline (speedup 1.0000x reference)
#include <cuda_runtime.h>
#include <cuda_bf16.h>
#include <cstdint>

#define N_NODES 50000
#define N_EDGES 1600000
#define DIM 128
#define NREL 24
#define NBASE 8
#define KTOT (NBASE*DIM + DIM)   // 1152

// ---------------- scratch (no allocations allowed) ----------------
__device__ int   g_cnt_node[N_NODES + 1];
__device__ int   g_row_ptr [N_NODES + 1];
__device__ int   g_cursor  [N_NODES];
__device__ int   g_cnt_nr  [N_NODES * NREL];
__device__ int   g_sorted  [N_EDGES];           // packed: (src<<5)|type
__device__ float g_h0[N_NODES * DIM];
__device__ float g_h1[N_NODES * DIM];
__device__ float g_T [(size_t)N_NODES * (NBASE * DIM)];   // 204.8 MB

// ---------------- kernels ----------------

__global__ void zero_counts_kernel() {
    int total = (N_NODES + 1) + N_NODES * NREL;
    for (int i = blockIdx.x * blockDim.x + threadIdx.x; i < total;
         i += gridDim.x * blockDim.x) {
        if (i <= N_NODES) g_cnt_node[i] = 0;
        else              g_cnt_nr[i - (N_NODES + 1)] = 0;
    }
}

__global__ void hist_kernel(const int* __restrict__ e_src,
                            const int* __restrict__ e_dst,
                            const int* __restrict__ e_typ, int E) {
    for (int e = blockIdx.x * blockDim.x + threadIdx.x; e < E;
         e += gridDim.x * blockDim.x) {
        int d = e_dst[e];
        int t = e_typ[e];
        atomicAdd(&g_cnt_node[d], 1);
        atomicAdd(&g_cnt_nr[d * NREL + t], 1);
    }
}

// single-block exclusive scan over g_cnt_node[0..N) -> g_row_ptr, g_cursor
__global__ void scan_kernel(int n) {
    __shared__ int warp_sums[32];
    int tid  = threadIdx.x;
    int lane = tid & 31;
    int wid  = tid >> 5;
    int carry = 0;
    for (int base = 0; base < n; base += 1024) {
        int idx = base + tid;
        int v = (idx < n) ? g_cnt_node[idx] : 0;
        // warp inclusive scan
        int x = v;
        #pragma unroll
        for (int d = 1; d < 32; d <<= 1) {
            int y = __shfl_up_sync(0xffffffffu, x, d);
            if (lane >= d) x += y;
        }
        if (lane == 31) warp_sums[wid] = x;
        __syncthreads();
        if (wid == 0) {
            int s = warp_sums[lane];
            #pragma unroll
            for (int d = 1; d < 32; d <<= 1) {
                int y = __shfl_up_sync(0xffffffffu, s, d);
                if (lane >= d) s += y;
            }
            warp_sums[lane] = s;   // inclusive over warp sums
        }
        __syncthreads();
        int offset = (wid > 0) ? warp_sums[wid - 1] : 0;
        int excl = x + offset - v + carry;
        if (idx < n) { g_row_ptr[idx] = excl; g_cursor[idx] = excl; }
        int total = warp_sums[31];
        __syncthreads();
        carry += total;
    }
    if (tid == 0) g_row_ptr[n] = carry;
}

__global__ void scatter_kernel(const int* __restrict__ e_src,
                               const int* __restrict__ e_dst,
                               const int* __restrict__ e_typ, int E) {
    for (int e = blockIdx.x * blockDim.x + threadIdx.x; e < E;
         e += gridDim.x * blockDim.x) {
        int d = e_dst[e];
        int pos = atomicAdd(&g_cursor[d], 1);
        g_sorted[pos] = (e_src[e] << 5) | e_typ[e];
    }
}

__global__ void embed_kernel(const int* __restrict__ x,
                             const float* __restrict__ table) {
    int n = blockIdx.x;
    int i = threadIdx.x;
    size_t row = (size_t)x[n] * DIM;
    g_h0[n * DIM + i] = table[row + i];
}

// 1 CTA per node, 128 threads = feature dims. Folds comp/cnt into the
// per-edge accumulation; writes T[n, b*128 + i].
__global__ void agg_kernel(const float* __restrict__ h,
                           const float* __restrict__ comp) {
    __shared__ float s_invc[NREL];
    __shared__ float s_w[NREL * NBASE];
    int n   = blockIdx.x;
    int tid = threadIdx.x;
    if (tid < NREL) {
        int c = g_cnt_nr[n * NREL + tid];
        s_invc[tid] = 1.0f / fmaxf((float)c, 1.0f);
    }
    __syncthreads();
    for (int idx = tid; idx < NREL * NBASE; idx += 128) {
        int r = idx >> 3;
        s_w[idx] = comp[idx] * s_invc[r];   // comp is [R,B] row-major
    }
    __syncthreads();

    float acc[NBASE];
    #pragma unroll
    for (int b = 0; b < NBASE; b++) acc[b] = 0.0f;

    int s = g_row_ptr[n], e = g_row_ptr[n + 1];
    for (int i = s; i < e; i++) {
        int p   = g_sorted[i];
        int src = p >> 5;
        int r   = p & 31;
        float hv = __ldg(&h[src * DIM + tid]);
        const float* wr = &s_w[r * NBASE];
        #pragma unroll
        for (int b = 0; b < NBASE; b++) acc[b] += hv * wr[b];
    }
    float* o = g_T + (size_t)n * (NBASE * DIM) + tid;
    #pragma unroll
    for (int b = 0; b < NBASE; b++) o[b * DIM] = acc[b];
}

// out[M,128] = T[M,1024] @ bases[1024,128] + Hin[M,128] @ root[128,128] + bias
// Tiled fp32 SGEMM: BM=128, BN=128, BK=16, 256 threads, 8x8 microtile.
__global__ __launch_bounds__(256, 2)
void gemm_kernel(const float* __restrict__ Tmat,
                 const float* __restrict__ Hin,
                 const float* __restrict__ bases,
                 const float* __restrict__ root,
                 const float* __restrict__ bias,
                 float* __restrict__ out,
                 int M, int doRelu) {
    __shared__ float As[16][128];
    __shared__ float Bs[16][128];

    int tid = threadIdx.x;
    int tx = tid & 15;          // 0..15 -> output col block of 8
    int ty = tid >> 4;          // 0..15 -> output row block of 8
    int rowBase = blockIdx.x * 128;

    int aRow = tid >> 1;        // 0..127
    int aCol = (tid & 1) * 8;   // 0 or 8
    int bRow = tid >> 4;        // 0..15
    int bCol = (tid & 15) * 8;

    float acc[8][8];
    #pragma unroll
    for (int i = 0; i < 8; i++)
        #pragma unroll
        for (int j = 0; j < 8; j++) acc[i][j] = 0.0f;

    const int NK1 = (NBASE * DIM) / 16;   // 64 tiles from T/bases
    const int NKT = KTOT / 16;            // 72 total

    for (int kt = 0; kt < NKT; kt++) {
        const float* Aptr; int lda; int kcol; const float* Bsrc;
        if (kt < NK1) { Aptr = Tmat; lda = NBASE * DIM; kcol = kt * 16;
                        Bsrc = bases + (size_t)kcol * DIM; }
        else          { Aptr = Hin;  lda = DIM; kcol = (kt - NK1) * 16;
                        Bsrc = root + (size_t)kcol * DIM; }

        int gr = rowBase + aRow;
        float4 a0, a1;
        if (gr < M) {
            const float* p = Aptr + (size_t)gr * lda + kcol + aCol;
            a0 = *(const float4*)(p);
            a1 = *(const float4*)(p + 4);
        } else {
            a0 = make_float4(0.f, 0.f, 0.f, 0.f);
            a1 = a0;
        }
        const float* q = Bsrc + bRow * DIM + bCol;
        float4 b0 = *(const float4*)(q);
        float4 b1 = *(const float4*)(q + 4);

        __syncthreads();
        As[aCol + 0][aRow] = a0.x; As[aCol + 1][aRow] = a0.y;
        As[aCol + 2][aRow] = a0.z; As[aCol + 3][aRow] = a0.w;
        As[aCol + 4][aRow] = a1.x; As[aCol + 5][aRow] = a1.y;
        As[aCol + 6][aRow] = a1.z; As[aCol + 7][aRow] = a1.w;
        *(float4*)&Bs[bRow][bCol]     = b0;
        *(float4*)&Bs[bRow][bCol + 4] = b1;
        __syncthreads();

        #pragma unroll
        for (int kk = 0; kk < 16; kk++) {
            float a[8], b[8];
            *(float4*)(a)     = *(const float4*)&As[kk][ty * 8];
            *(float4*)(a + 4) = *(const float4*)&As[kk][ty * 8 + 4];
            *(float4*)(b)     = *(const float4*)&Bs[kk][tx * 8];
            *(float4*)(b + 4) = *(const float4*)&Bs[kk][tx * 8 + 4];
            #pragma unroll
            for (int i = 0; i < 8; i++)
                #pragma unroll
                for (int j = 0; j < 8; j++)
                    acc[i][j] = fmaf(a[i], b[j], acc[i][j]);
        }
    }

    #pragma unroll
    for (int i = 0; i < 8; i++) {
        int r = rowBase + ty * 8 + i;
        if (r >= M) break;
        #pragma unroll
        for (int j = 0; j < 8; j++) {
            int c = tx * 8 + j;
            float v = acc[i][j] + bias[c];
            if (doRelu) v = fmaxf(v, 0.0f);
            out[(size_t)r * DIM + c] = v;
        }
    }
}

// ---------------- launcher ----------------
extern "C" void kernel_launch(void* const* d_in, const int* in_sizes, int n_in,
                              void* d_out, int out_size) {
    const int*   x      = (const int*)  d_in[0];
    const int*   eidx   = (const int*)  d_in[1];
    const int*   etyp   = (const int*)  d_in[2];
    const float* table  = (const float*)d_in[3];
    const float* comp1  = (const float*)d_in[4];
    const float* bases1 = (const float*)d_in[5];
    const float* root1  = (const float*)d_in[6];
    const float* bias1  = (const float*)d_in[7];
    const float* comp2  = (const float*)d_in[8];
    const float* bases2 = (const float*)d_in[9];
    const float* root2  = (const float*)d_in[10];
    const float* bias2  = (const float*)d_in[11];

    const int E = in_sizes[2];          // 1,600,000
    const int N = in_sizes[0];          // 50,000
    const int* e_src = eidx;            // edge_index[0]
    const int* e_dst = eidx + E;        // edge_index[1]
    float* out = (float*)d_out;

    // device pointers for scratch
    float* h0; float* h1; float* Tm;
    cudaGetSymbolAddress((void**)&h0, g_h0);
    cudaGetSymbolAddress((void**)&h1, g_h1);
    cudaGetSymbolAddress((void**)&Tm, g_T);

    int eBlocks = (E + 255) / 256;
    int zBlocks = ((N + 1) + N * NREL + 255) / 256;
    int gBlocks = (N + 127) / 128;

    // --- build dst-sorted CSR (shared by both layers) ---
    zero_counts_kernel<<<zBlocks, 256>>>();
    hist_kernel<<<eBlocks, 256>>>(e_src, e_dst, etyp, E);
    scan_kernel<<<1, 1024>>>(N);
    scatter_kernel<<<eBlocks, 256>>>(e_src, e_dst, etyp, E);

    // --- embedding lookup ---
    embed_kernel<<<N, DIM>>>(x, table);

    // --- layer 1 ---
    agg_kernel<<<N, DIM>>>(h0, comp1);
    gemm_kernel<<<gBlocks, 256>>>(Tm, h0, bases1, root1, bias1, h1, N, 1);

    // --- layer 2 ---
    agg_kernel<<<N, DIM>>>(h1, comp2);
    gemm_kernel<<<gBlocks, 256>>>(Tm, h1, bases2, root2, bias2, out, N, 0);
}

// round 2
// speedup vs baseline: 1.8409x; 1.8409x over previous
#include <cuda_runtime.h>
#include <cuda_bf16.h>
#include <cstdint>

#define N_NODES 50000
#define N_EDGES 1600000
#define DIM 128
#define NREL 24
#define NBASE 8
#define KTOT (NBASE*DIM + DIM)   // 1152

// ---------------- scratch (no allocations allowed) ----------------
__device__ int   g_cnt_node[N_NODES + 1];
__device__ int   g_row_ptr [N_NODES + 1];
__device__ int   g_cursor  [N_NODES];
__device__ int   g_cnt_nr  [N_NODES * NREL];
__device__ int   g_sorted  [N_EDGES];           // packed: (src<<5)|type
__device__ __align__(16) float g_h0[N_NODES * DIM];
__device__ __align__(16) float g_h1[N_NODES * DIM];
__device__ __align__(16) float g_T [(size_t)N_NODES * (NBASE * DIM)];   // 204.8 MB

// ---------------- graph preprocessing ----------------

__global__ void zero_nr_kernel() {
    int total = N_NODES * NREL;
    for (int i = blockIdx.x * blockDim.x + threadIdx.x; i < total;
         i += gridDim.x * blockDim.x)
        g_cnt_nr[i] = 0;
}

__global__ void hist_kernel(const int* __restrict__ e_dst,
                            const int* __restrict__ e_typ, int E) {
    for (int e = blockIdx.x * blockDim.x + threadIdx.x; e < E;
         e += gridDim.x * blockDim.x) {
        atomicAdd(&g_cnt_nr[e_dst[e] * NREL + e_typ[e]], 1);
    }
}

__global__ void node_cnt_kernel() {
    int n = blockIdx.x * blockDim.x + threadIdx.x;
    if (n >= N_NODES) return;
    int s = 0;
    const int* p = &g_cnt_nr[n * NREL];
    #pragma unroll
    for (int t = 0; t < NREL; t++) s += p[t];
    g_cnt_node[n] = s;
}

// single-block exclusive scan over g_cnt_node[0..N) -> g_row_ptr, g_cursor
__global__ void scan_kernel(int n) {
    __shared__ int warp_sums[32];
    int tid  = threadIdx.x;
    int lane = tid & 31;
    int wid  = tid >> 5;
    int carry = 0;
    for (int base = 0; base < n; base += 1024) {
        int idx = base + tid;
        int v = (idx < n) ? g_cnt_node[idx] : 0;
        int x = v;
        #pragma unroll
        for (int d = 1; d < 32; d <<= 1) {
            int y = __shfl_up_sync(0xffffffffu, x, d);
            if (lane >= d) x += y;
        }
        if (lane == 31) warp_sums[wid] = x;
        __syncthreads();
        if (wid == 0) {
            int s = warp_sums[lane];
            #pragma unroll
            for (int d = 1; d < 32; d <<= 1) {
                int y = __shfl_up_sync(0xffffffffu, s, d);
                if (lane >= d) s += y;
            }
            warp_sums[lane] = s;
        }
        __syncthreads();
        int offset = (wid > 0) ? warp_sums[wid - 1] : 0;
        int excl = x + offset - v + carry;
        if (idx < n) { g_row_ptr[idx] = excl; g_cursor[idx] = excl; }
        int total = warp_sums[31];
        __syncthreads();
        carry += total;
    }
    if (tid == 0) g_row_ptr[n] = carry;
}

__global__ void scatter_kernel(const int* __restrict__ e_src,
                               const int* __restrict__ e_dst,
                               const int* __restrict__ e_typ, int E) {
    for (int e = blockIdx.x * blockDim.x + threadIdx.x; e < E;
         e += gridDim.x * blockDim.x) {
        int d = e_dst[e];
        int pos = atomicAdd(&g_cursor[d], 1);
        g_sorted[pos] = (e_src[e] << 5) | e_typ[e];
    }
}

__global__ void embed_kernel(const int* __restrict__ x,
                             const float* __restrict__ table) {
    int n = blockIdx.x;
    int i = threadIdx.x;
    size_t row = (size_t)x[n] * DIM;
    g_h0[n * DIM + i] = table[row + i];
}

// ---------------- aggregation: 1 CTA/node, 128 threads = feature lanes ----
__global__ void agg_kernel(const float* __restrict__ h,
                           const float* __restrict__ comp) {
    __shared__ float s_w[NREL * NBASE];
    int n   = blockIdx.x;
    int tid = threadIdx.x;
    __shared__ float s_invc[NREL];
    if (tid < NREL) {
        int c = g_cnt_nr[n * NREL + tid];
        s_invc[tid] = 1.0f / fmaxf((float)c, 1.0f);
    }
    __syncthreads();
    for (int idx = tid; idx < NREL * NBASE; idx += 128) {
        int r = idx >> 3;
        s_w[idx] = comp[idx] * s_invc[r];
    }
    __syncthreads();

    float acc[NBASE];
    #pragma unroll
    for (int b = 0; b < NBASE; b++) acc[b] = 0.0f;

    int s = g_row_ptr[n], e = g_row_ptr[n + 1];
    int i = s;
    // unrolled-by-4: 4 independent row gathers in flight (MLP=4)
    for (; i + 4 <= e; i += 4) {
        int p0 = g_sorted[i + 0];
        int p1 = g_sorted[i + 1];
        int p2 = g_sorted[i + 2];
        int p3 = g_sorted[i + 3];
        float v0 = __ldg(&h[(p0 >> 5) * DIM + tid]);
        float v1 = __ldg(&h[(p1 >> 5) * DIM + tid]);
        float v2 = __ldg(&h[(p2 >> 5) * DIM + tid]);
        float v3 = __ldg(&h[(p3 >> 5) * DIM + tid]);
        const float* w0 = &s_w[(p0 & 31) * NBASE];
        const float* w1 = &s_w[(p1 & 31) * NBASE];
        const float* w2 = &s_w[(p2 & 31) * NBASE];
        const float* w3 = &s_w[(p3 & 31) * NBASE];
        #pragma unroll
        for (int b = 0; b < NBASE; b++) {
            acc[b] += v0 * w0[b];
            acc[b] += v1 * w1[b];
            acc[b] += v2 * w2[b];
            acc[b] += v3 * w3[b];
        }
    }
    for (; i < e; i++) {
        int p = g_sorted[i];
        float hv = __ldg(&h[(p >> 5) * DIM + tid]);
        const float* wr = &s_w[(p & 31) * NBASE];
        #pragma unroll
        for (int b = 0; b < NBASE; b++) acc[b] += hv * wr[b];
    }
    float* o = g_T + (size_t)n * (NBASE * DIM) + tid;
    #pragma unroll
    for (int b = 0; b < NBASE; b++) o[b * DIM] = acc[b];
}

// ---------------- tensor-core GEMM (tf32 mma.sync) ----------------
// out[M,128] = [T | Hin][M,1152] @ [bases ; root][1152,128] + bias (opt relu)
// BM=128, BN=128, BK=16; 8 warps; warp tile 32x64 (4x2 warp grid);
// mma m16n8k8: per warp 2 m-tiles x 8 n-tiles.

__device__ __forceinline__ uint32_t f2tf32(float x) {
    uint32_t u;
    asm("cvt.rna.tf32.f32 %0, %1;" : "=r"(u) : "f"(x));
    return u;
}

__device__ __forceinline__ void mma_tf32(float c[4], const uint32_t a[4],
                                         uint32_t b0, uint32_t b1) {
    asm volatile(
        "mma.sync.aligned.m16n8k8.row.col.f32.tf32.tf32.f32 "
        "{%0,%1,%2,%3}, {%4,%5,%6,%7}, {%8,%9}, {%0,%1,%2,%3};\n"
        : "+f"(c[0]), "+f"(c[1]), "+f"(c[2]), "+f"(c[3])
        : "r"(a[0]), "r"(a[1]), "r"(a[2]), "r"(a[3]), "r"(b0), "r"(b1));
}

#define SPAD 132   // 128 + 4 padding (keeps 16B alignment, breaks conflicts)

__global__ __launch_bounds__(256, 2)
void gemm_tc_kernel(const float* __restrict__ Tmat,
                    const float* __restrict__ Hin,
                    const float* __restrict__ bases,
                    const float* __restrict__ root,
                    const float* __restrict__ bias,
                    float* __restrict__ out,
                    int M, int doRelu) {
    __shared__ uint32_t As[16][SPAD];   // [k][m]
    __shared__ uint32_t Bs[16][SPAD];   // [k][n]

    int tid  = threadIdx.x;
    int lane = tid & 31;
    int wid  = tid >> 5;
    int wm = (wid >> 1) * 32;     // warp m offset (0,32,64,96)
    int wn = (wid & 1) * 64;      // warp n offset (0,64)
    int g  = lane >> 2;           // 0..7
    int tg = lane & 3;            // 0..3
    int rowBase = blockIdx.x * 128;

    int aRow = tid >> 1;          // 0..127
    int aCol = (tid & 1) * 8;     // 0 or 8
    int bRow = tid >> 4;          // 0..15
    int bCol = (tid & 15) * 8;

    float acc[2][8][4];
    #pragma unroll
    for (int mt = 0; mt < 2; mt++)
        #pragma unroll
        for (int nt = 0; nt < 8; nt++)
            #pragma unroll
            for (int q = 0; q < 4; q++) acc[mt][nt][q] = 0.0f;

    const int NK1 = (NBASE * DIM) / 16;   // 64
    const int NKT = KTOT / 16;            // 72

    float ar[8], br[8];

    // prefetch tile 0
    {
        const float* p = Tmat + (size_t)(rowBase + aRow) * (NBASE * DIM) + aCol;
        if (rowBase + aRow < M) {
            float4 a0 = *(const float4*)(p);
            float4 a1 = *(const float4*)(p + 4);
            ar[0]=a0.x; ar[1]=a0.y; ar[2]=a0.z; ar[3]=a0.w;
            ar[4]=a1.x; ar[5]=a1.y; ar[6]=a1.z; ar[7]=a1.w;
        } else {
            #pragma unroll
            for (int j = 0; j < 8; j++) ar[j] = 0.0f;
        }
        const float* q = bases + (size_t)bRow * DIM + bCol;
        float4 b0 = *(const float4*)(q);
        float4 b1 = *(const float4*)(q + 4);
        br[0]=b0.x; br[1]=b0.y; br[2]=b0.z; br[3]=b0.w;
        br[4]=b1.x; br[5]=b1.y; br[6]=b1.z; br[7]=b1.w;
    }

    for (int kt = 0; kt < NKT; kt++) {
        __syncthreads();
        #pragma unroll
        for (int j = 0; j < 8; j++) As[aCol + j][aRow] = f2tf32(ar[j]);
        {
            uint4 v0, v1;
            v0.x = f2tf32(br[0]); v0.y = f2tf32(br[1]);
            v0.z = f2tf32(br[2]); v0.w = f2tf32(br[3]);
            v1.x = f2tf32(br[4]); v1.y = f2tf32(br[5]);
            v1.z = f2tf32(br[6]); v1.w = f2tf32(br[7]);
            *(uint4*)&Bs[bRow][bCol]     = v0;
            *(uint4*)&Bs[bRow][bCol + 4] = v1;
        }
        __syncthreads();

        // prefetch next tile
        if (kt + 1 < NKT) {
            int kn = kt + 1;
            const float* Aptr; int lda; int kcol; const float* Bsrc;
            if (kn < NK1) { Aptr = Tmat; lda = NBASE * DIM; kcol = kn * 16;
                            Bsrc = bases + (size_t)kcol * DIM; }
            else          { Aptr = Hin;  lda = DIM; kcol = (kn - NK1) * 16;
                            Bsrc = root + (size_t)kcol * DIM; }
            if (rowBase + aRow < M) {
                const float* p = Aptr + (size_t)(rowBase + aRow) * lda + kcol + aCol;
                float4 a0 = *(const float4*)(p);
                float4 a1 = *(const float4*)(p + 4);
                ar[0]=a0.x; ar[1]=a0.y; ar[2]=a0.z; ar[3]=a0.w;
                ar[4]=a1.x; ar[5]=a1.y; ar[6]=a1.z; ar[7]=a1.w;
            } else {
                #pragma unroll
                for (int j = 0; j < 8; j++) ar[j] = 0.0f;
            }
            const float* q = Bsrc + (size_t)bRow * DIM + bCol;
            float4 b0 = *(const float4*)(q);
            float4 b1 = *(const float4*)(q + 4);
            br[0]=b0.x; br[1]=b0.y; br[2]=b0.z; br[3]=b0.w;
            br[4]=b1.x; br[5]=b1.y; br[6]=b1.z; br[7]=b1.w;
        }

        // compute: two k-steps of 8
        #pragma unroll
        for (int ks = 0; ks < 16; ks += 8) {
            uint32_t af[2][4];
            #pragma unroll
            for (int mt = 0; mt < 2; mt++) {
                int m0 = wm + mt * 16;
                af[mt][0] = As[ks + tg    ][m0 + g];
                af[mt][1] = As[ks + tg    ][m0 + g + 8];
                af[mt][2] = As[ks + tg + 4][m0 + g];
                af[mt][3] = As[ks + tg + 4][m0 + g + 8];
            }
            #pragma unroll
            for (int nt = 0; nt < 8; nt++) {
                int n0 = wn + nt * 8 + g;
                uint32_t b0 = Bs[ks + tg    ][n0];
                uint32_t b1 = Bs[ks + tg + 4][n0];
                mma_tf32(acc[0][nt], af[0], b0, b1);
                mma_tf32(acc[1][nt], af[1], b0, b1);
            }
        }
    }

    // epilogue: bias + optional relu, write float2 pairs
    #pragma unroll
    for (int mt = 0; mt < 2; mt++) {
        int r0 = rowBase + wm + mt * 16 + g;
        #pragma unroll
        for (int nt = 0; nt < 8; nt++) {
            int col = wn + nt * 8 + 2 * tg;
            float bx = __ldg(&bias[col]);
            float by = __ldg(&bias[col + 1]);
            float v0 = acc[mt][nt][0] + bx;
            float v1 = acc[mt][nt][1] + by;
            float v2 = acc[mt][nt][2] + bx;
            float v3 = acc[mt][nt][3] + by;
            if (doRelu) {
                v0 = fmaxf(v0, 0.0f); v1 = fmaxf(v1, 0.0f);
                v2 = fmaxf(v2, 0.0f); v3 = fmaxf(v3, 0.0f);
            }
            if (r0 < M)
                *(float2*)&out[(size_t)r0 * DIM + col] = make_float2(v0, v1);
            if (r0 + 8 < M)
                *(float2*)&out[(size_t)(r0 + 8) * DIM + col] = make_float2(v2, v3);
        }
    }
}

// ---------------- launcher ----------------
extern "C" void kernel_launch(void* const* d_in, const int* in_sizes, int n_in,
                              void* d_out, int out_size) {
    const int*   x      = (const int*)  d_in[0];
    const int*   eidx   = (const int*)  d_in[1];
    const int*   etyp   = (const int*)  d_in[2];
    const float* table  = (const float*)d_in[3];
    const float* comp1  = (const float*)d_in[4];
    const float* bases1 = (const float*)d_in[5];
    const float* root1  = (const float*)d_in[6];
    const float* bias1  = (const float*)d_in[7];
    const float* comp2  = (const float*)d_in[8];
    const float* bases2 = (const float*)d_in[9];
    const float* root2  = (const float*)d_in[10];
    const float* bias2  = (const float*)d_in[11];

    const int E = in_sizes[2];
    const int N = in_sizes[0];
    const int* e_src = eidx;
    const int* e_dst = eidx + E;
    float* out = (float*)d_out;

    float* h0; float* h1; float* Tm;
    cudaGetSymbolAddress((void**)&h0, g_h0);
    cudaGetSymbolAddress((void**)&h1, g_h1);
    cudaGetSymbolAddress((void**)&Tm, g_T);

    int eBlocks = (E + 255) / 256;
    int zBlocks = (N * NREL + 255) / 256;
    int nBlocks = (N + 255) / 256;
    int gBlocks = (N + 127) / 128;

    // --- build dst-sorted CSR (shared by both layers) ---
    zero_nr_kernel<<<zBlocks, 256>>>();
    hist_kernel<<<eBlocks, 256>>>(e_dst, etyp, E);
    node_cnt_kernel<<<nBlocks, 256>>>();
    scan_kernel<<<1, 1024>>>(N);
    scatter_kernel<<<eBlocks, 256>>>(e_src, e_dst, etyp, E);

    // --- embedding lookup ---
    embed_kernel<<<N, DIM>>>(x, table);

    // --- layer 1 ---
    agg_kernel<<<N, DIM>>>(h0, comp1);
    gemm_tc_kernel<<<gBlocks, 256>>>(Tm, h0, bases1, root1, bias1, h1, N, 1);

    // --- layer 2 ---
    agg_kernel<<<N, DIM>>>(h1, comp2);
    gemm_tc_kernel<<<gBlocks, 256>>>(Tm, h1, bases2, root2, bias2, out, N, 0);
}

// round 6
// speedup vs baseline: 1.9701x; 1.0702x over previous
#include <cuda_runtime.h>
#include <cuda_bf16.h>
#include <cstdint>

#define N_NODES 50000
#define N_EDGES 1600000
#define DIM 128
#define NREL 24
#define NBASE 8
#define KTOT 1152              // 8*128 basis cols + 128 root cols
#define BK 32
#define NKT32 (KTOT / BK)      // 36

// ---------------- scratch ----------------
__device__ int   g_cnt_node[N_NODES + 1];
__device__ int   g_row_ptr [N_NODES + 1];
__device__ int   g_cursor  [N_NODES];
__device__ int   g_cnt_nr  [N_NODES * NREL];
__device__ int   g_sorted  [N_EDGES];
__device__ int   g_blk     [64];
__device__ __align__(16) float g_h0[N_NODES * DIM];
__device__ __align__(16) float g_h1[N_NODES * DIM];
__device__ __align__(16) float g_T [(size_t)N_NODES * KTOT];   // 230.4 MB
__device__ __align__(16) float g_Bp1[KTOT * DIM];              // tf32-rounded [k][n]
__device__ __align__(16) float g_Bp2[KTOT * DIM];

// ---------------- helpers ----------------
__device__ __forceinline__ uint32_t smem_u32(const void* p) {
    uint32_t a;
    asm("{ .reg .u64 t; cvta.to.shared.u64 t, %1; cvt.u32.u64 %0, t; }"
        : "=r"(a) : "l"(p));
    return a;
}
__device__ __forceinline__ float tf32r(float x) {
    uint32_t u;
    asm("cvt.rna.tf32.f32 %0, %1;" : "=r"(u) : "f"(x));
    return __uint_as_float(u);
}
__device__ __forceinline__ void cp16(uint32_t dst, const void* src, int sz) {
    asm volatile("cp.async.cg.shared.global [%0], [%1], 16, %2;"
                 :: "r"(dst), "l"(src), "r"(sz) : "memory");
}
#define CP_COMMIT() asm volatile("cp.async.commit_group;" ::: "memory")
#define CP_WAIT1()  asm volatile("cp.async.wait_group 1;" ::: "memory")
#define CP_WAIT0()  asm volatile("cp.async.wait_group 0;" ::: "memory")

__device__ __forceinline__ void mma_tf32(float c[4], const uint32_t a[4],
                                         uint32_t b0, uint32_t b1) {
    asm volatile(
        "mma.sync.aligned.m16n8k8.row.col.f32.tf32.tf32.f32 "
        "{%0,%1,%2,%3}, {%4,%5,%6,%7}, {%8,%9}, {%0,%1,%2,%3};\n"
        : "+f"(c[0]), "+f"(c[1]), "+f"(c[2]), "+f"(c[3])
        : "r"(a[0]), "r"(a[1]), "r"(a[2]), "r"(a[3]), "r"(b0), "r"(b1));
}

// ---------------- graph preprocessing ----------------

__global__ void zero_nr_kernel() {
    int total = N_NODES * NREL;
    for (int i = blockIdx.x * blockDim.x + threadIdx.x; i < total;
         i += gridDim.x * blockDim.x)
        g_cnt_nr[i] = 0;
}

__global__ void hist_kernel(const int* __restrict__ e_dst,
                            const int* __restrict__ e_typ, int E) {
    for (int e = blockIdx.x * blockDim.x + threadIdx.x; e < E;
         e += gridDim.x * blockDim.x)
        atomicAdd(&g_cnt_nr[e_dst[e] * NREL + e_typ[e]], 1);
}

__global__ void csr_part1() {
    int n = blockIdx.x * 1024 + threadIdx.x;
    int v = 0;
    if (n < N_NODES) {
        const int* p = &g_cnt_nr[n * NREL];
        #pragma unroll
        for (int t = 0; t < NREL; t++) v += p[t];
        g_cnt_node[n] = v;
    }
    __shared__ int ws[32];
    int lane = threadIdx.x & 31, wid = threadIdx.x >> 5;
    int x = v;
    #pragma unroll
    for (int d = 16; d > 0; d >>= 1) x += __shfl_down_sync(0xffffffffu, x, d);
    if (lane == 0) ws[wid] = x;
    __syncthreads();
    if (wid == 0) {
        int s = ws[lane];
        #pragma unroll
        for (int d = 16; d > 0; d >>= 1) s += __shfl_down_sync(0xffffffffu, s, d);
        if (lane == 0) g_blk[blockIdx.x] = s;
    }
}

__global__ void csr_part2(int nblk) {
    if (threadIdx.x == 0) {
        int s = 0;
        for (int i = 0; i < nblk; i++) { int t = g_blk[i]; g_blk[i] = s; s += t; }
    }
}

__global__ void csr_part3() {
    __shared__ int ws[32];
    int tid = threadIdx.x, lane = tid & 31, wid = tid >> 5;
    int n = blockIdx.x * 1024 + tid;
    int v = (n < N_NODES) ? g_cnt_node[n] : 0;
    int x = v;
    #pragma unroll
    for (int d = 1; d < 32; d <<= 1) {
        int y = __shfl_up_sync(0xffffffffu, x, d);
        if (lane >= d) x += y;
    }
    if (lane == 31) ws[wid] = x;
    __syncthreads();
    if (wid == 0) {
        int s = ws[lane];
        #pragma unroll
        for (int d = 1; d < 32; d <<= 1) {
            int y = __shfl_up_sync(0xffffffffu, s, d);
            if (lane >= d) s += y;
        }
        ws[lane] = s;
    }
    __syncthreads();
    int off = (wid > 0 ? ws[wid - 1] : 0) + g_blk[blockIdx.x];
    int excl = x - v + off;
    if (n < N_NODES) { g_row_ptr[n] = excl; g_cursor[n] = excl; }
    if (n == N_NODES - 1) g_row_ptr[N_NODES] = excl + v;
}

__global__ void scatter_kernel(const int* __restrict__ e_src,
                               const int* __restrict__ e_dst,
                               const int* __restrict__ e_typ, int E) {
    for (int e = blockIdx.x * blockDim.x + threadIdx.x; e < E;
         e += gridDim.x * blockDim.x) {
        int pos = atomicAdd(&g_cursor[e_dst[e]], 1);
        g_sorted[pos] = (e_src[e] << 5) | e_typ[e];
    }
}

__global__ void embed_kernel(const int* __restrict__ x,
                             const float* __restrict__ table) {
    int n = blockIdx.x, i = threadIdx.x;
    g_h0[n * DIM + i] = table[(size_t)x[n] * DIM + i];
}

// Bp[k][n] = tf32_round(k<1024 ? bases[k][n] : root[k-1024][n])
__global__ void prep_b_kernel(const float* __restrict__ bases,
                              const float* __restrict__ root,
                              float* __restrict__ Bp) {
    int k = blockIdx.x, n = threadIdx.x;
    float v = (k < NBASE * DIM) ? bases[k * DIM + n]
                                : root[(k - NBASE * DIM) * DIM + n];
    Bp[k * DIM + n] = tf32r(v);
}

// ---------------- aggregation: 1 CTA/node, 128 feature lanes ----------
__global__ void agg_kernel(const float* __restrict__ h,
                           const float* __restrict__ comp) {
    __shared__ float s_w[NREL * NBASE];
    __shared__ float s_invc[NREL];
    int n = blockIdx.x, tid = threadIdx.x;
    if (tid < NREL) {
        int c = g_cnt_nr[n * NREL + tid];
        s_invc[tid] = 1.0f / fmaxf((float)c, 1.0f);
    }
    __syncthreads();
    for (int idx = tid; idx < NREL * NBASE; idx += 128)
        s_w[idx] = comp[idx] * s_invc[idx >> 3];
    __syncthreads();

    float acc[NBASE];
    #pragma unroll
    for (int b = 0; b < NBASE; b++) acc[b] = 0.0f;

    int s = g_row_ptr[n], e = g_row_ptr[n + 1];
    int i = s;
    for (; i + 8 <= e; i += 8) {
        int p[8];
        float v[8];
        #pragma unroll
        for (int u = 0; u < 8; u++) p[u] = g_sorted[i + u];
        #pragma unroll
        for (int u = 0; u < 8; u++)
            v[u] = __ldg(&h[(p[u] >> 5) * DIM + tid]);
        #pragma unroll
        for (int u = 0; u < 8; u++) {
            const float* wr = &s_w[(p[u] & 31) * NBASE];
            #pragma unroll
            for (int b = 0; b < NBASE; b++) acc[b] += v[u] * wr[b];
        }
    }
    for (; i < e; i++) {
        int p = g_sorted[i];
        float hv = __ldg(&h[(p >> 5) * DIM + tid]);
        const float* wr = &s_w[(p & 31) * NBASE];
        #pragma unroll
        for (int b = 0; b < NBASE; b++) acc[b] += hv * wr[b];
    }
    float* o = g_T + (size_t)n * KTOT + tid;
    #pragma unroll
    for (int b = 0; b < NBASE; b++) o[b * DIM] = tf32r(acc[b]);
    o[NBASE * DIM] = tf32r(__ldg(&h[n * DIM + tid]));   // root-term tail
}

// ---------------- tf32 mma.sync GEMM with cp.async double buffer ------
// out[M,128] = A[M,1152] @ Bp[1152,128] + bias (opt relu)
// BM=128, BN=128, BK=32; 256 threads, 8 warps (4x2), warp tile 32x64.
// As[s][m][k]: stride 36 (conflict-free: bank=(4g+tg)%32 all distinct)
// Bs[s][k][n]: stride 136 (bank=(8tg+g)%32 all distinct)
#define AS_STRIDE 36
#define BS_STRIDE 136
#define AS_FLOATS (128 * AS_STRIDE)          // per stage
#define BS_FLOATS (BK * BS_STRIDE)
#define GEMM_SMEM ((2 * AS_FLOATS + 2 * BS_FLOATS) * 4)   // 71,680 B

__global__ __launch_bounds__(256)
void gemm_tc(const float* __restrict__ A,
             const float* __restrict__ Bp,
             const float* __restrict__ bias,
             float* __restrict__ out, int M, int doRelu) {
    extern __shared__ __align__(16) uint32_t smbuf[];
    uint32_t* AsBase = smbuf;                   // 2 stages
    uint32_t* BsBase = smbuf + 2 * AS_FLOATS;

    int tid  = threadIdx.x;
    int lane = tid & 31;
    int wid  = tid >> 5;
    int wm = (wid >> 1) * 32;     // warp m offset
    int wn = (wid & 1) * 64;      // warp n offset
    int g  = lane >> 2;           // 0..7
    int tg = lane & 3;            // 0..3
    int m0 = blockIdx.x * 128;

    // cp.async thread mapping
    int aRow  = tid >> 1;                // 0..127
    int aCol0 = (tid & 1) * 16;          // 0 or 16 (floats)
    int bRow  = tid >> 3;                // 0..31
    int bCol0 = (tid & 7) * 16;          // 0..112 (floats)

    int aSz = (m0 + aRow < M) ? 16 : 0;  // zero-fill OOB rows
    const float* aSrcBase = A + (size_t)(m0 + aRow) * KTOT + aCol0;
    uint32_t aDst0 = smem_u32(&AsBase[aRow * AS_STRIDE + aCol0]);
    uint32_t bDst0 = smem_u32(&BsBase[bRow * BS_STRIDE + bCol0]);

    float acc[2][8][4];
    #pragma unroll
    for (int mt = 0; mt < 2; mt++) {
        #pragma unroll
        for (int nt = 0; nt < 8; nt++) {
            #pragma unroll
            for (int q = 0; q < 4; q++) acc[mt][nt][q] = 0.0f;
        }
    }

    // issue stage for k-tile kt into buffer s
    auto issue = [&](int s, int kt) {
        const float* as = aSrcBase + kt * BK;
        uint32_t ad = aDst0 + s * AS_FLOATS * 4;
        #pragma unroll
        for (int c = 0; c < 4; c++)
            cp16(ad + c * 16, as + c * 4, aSz);
        const float* bs = Bp + (size_t)(kt * BK + bRow) * DIM + bCol0;
        uint32_t bd = bDst0 + s * BS_FLOATS * 4;
        #pragma unroll
        for (int c = 0; c < 4; c++)
            cp16(bd + c * 16, bs + c * 4, 16);
        CP_COMMIT();
    };

    issue(0, 0);

    for (int kt = 0; kt < NKT32; kt++) {
        int cur = kt & 1;
        if (kt + 1 < NKT32) {
            issue((kt + 1) & 1, kt + 1);
            CP_WAIT1();
        } else {
            CP_WAIT0();
        }
        __syncthreads();

        const uint32_t* Asb = AsBase + cur * AS_FLOATS;
        const uint32_t* Bsb = BsBase + cur * BS_FLOATS;

        #pragma unroll
        for (int ks = 0; ks < BK; ks += 8) {
            uint32_t af[2][4];
            #pragma unroll
            for (int mt = 0; mt < 2; mt++) {
                int mm = wm + mt * 16 + g;
                af[mt][0] = Asb[(mm)     * AS_STRIDE + ks + tg];
                af[mt][1] = Asb[(mm + 8) * AS_STRIDE + ks + tg];
                af[mt][2] = Asb[(mm)     * AS_STRIDE + ks + tg + 4];
                af[mt][3] = Asb[(mm + 8) * AS_STRIDE + ks + tg + 4];
            }
            #pragma unroll
            for (int nt = 0; nt < 8; nt++) {
                int n0 = wn + nt * 8 + g;
                uint32_t b0 = Bsb[(ks + tg)     * BS_STRIDE + n0];
                uint32_t b1 = Bsb[(ks + tg + 4) * BS_STRIDE + n0];
                mma_tf32(acc[0][nt], af[0], b0, b1);
                mma_tf32(acc[1][nt], af[1], b0, b1);
            }
        }
        __syncthreads();
    }

    // epilogue: bias + optional relu
    #pragma unroll
    for (int mt = 0; mt < 2; mt++) {
        int r0 = m0 + wm + mt * 16 + g;
        #pragma unroll
        for (int nt = 0; nt < 8; nt++) {
            int col = wn + nt * 8 + 2 * tg;
            float bx = __ldg(&bias[col]), by = __ldg(&bias[col + 1]);
            float v0 = acc[mt][nt][0] + bx, v1 = acc[mt][nt][1] + by;
            float v2 = acc[mt][nt][2] + bx, v3 = acc[mt][nt][3] + by;
            if (doRelu) {
                v0 = fmaxf(v0, 0.f); v1 = fmaxf(v1, 0.f);
                v2 = fmaxf(v2, 0.f); v3 = fmaxf(v3, 0.f);
            }
            if (r0 < M)
                *(float2*)&out[(size_t)r0 * DIM + col] = make_float2(v0, v1);
            if (r0 + 8 < M)
                *(float2*)&out[(size_t)(r0 + 8) * DIM + col] = make_float2(v2, v3);
        }
    }
}

// ---------------- launcher ----------------
extern "C" void kernel_launch(void* const* d_in, const int* in_sizes, int n_in,
                              void* d_out, int out_size) {
    const int*   x      = (const int*)  d_in[0];
    const int*   eidx   = (const int*)  d_in[1];
    const int*   etyp   = (const int*)  d_in[2];
    const float* table  = (const float*)d_in[3];
    const float* comp1  = (const float*)d_in[4];
    const float* bases1 = (const float*)d_in[5];
    const float* root1  = (const float*)d_in[6];
    const float* bias1  = (const float*)d_in[7];
    const float* comp2  = (const float*)d_in[8];
    const float* bases2 = (const float*)d_in[9];
    const float* root2  = (const float*)d_in[10];
    const float* bias2  = (const float*)d_in[11];

    const int E = in_sizes[2];
    const int N = in_sizes[0];
    const int* e_src = eidx;
    const int* e_dst = eidx + E;
    float* out = (float*)d_out;

    float *h0, *h1, *Tm, *Bp1, *Bp2;
    cudaGetSymbolAddress((void**)&h0,  g_h0);
    cudaGetSymbolAddress((void**)&h1,  g_h1);
    cudaGetSymbolAddress((void**)&Tm,  g_T);
    cudaGetSymbolAddress((void**)&Bp1, g_Bp1);
    cudaGetSymbolAddress((void**)&Bp2, g_Bp2);

    cudaFuncSetAttribute(gemm_tc,
                         cudaFuncAttributeMaxDynamicSharedMemorySize, GEMM_SMEM);

    int eBlocks = (E + 255) / 256;
    int zBlocks = (N * NREL + 255) / 256;
    int sBlocks = (N + 1023) / 1024;
    int gBlocks = (N + 127) / 128;

    // CSR build
    zero_nr_kernel<<<zBlocks, 256>>>();
    hist_kernel<<<eBlocks, 256>>>(e_dst, etyp, E);
    csr_part1<<<sBlocks, 1024>>>();
    csr_part2<<<1, 32>>>(sBlocks);
    csr_part3<<<sBlocks, 1024>>>();
    scatter_kernel<<<eBlocks, 256>>>(e_src, e_dst, etyp, E);

    // embedding + weight prep
    embed_kernel<<<N, DIM>>>(x, table);
    prep_b_kernel<<<KTOT, DIM>>>(bases1, root1, Bp1);
    prep_b_kernel<<<KTOT, DIM>>>(bases2, root2, Bp2);

    // layer 1
    agg_kernel<<<N, DIM>>>(h0, comp1);
    gemm_tc<<<gBlocks, 256, GEMM_SMEM>>>(Tm, Bp1, bias1, h1, N, 1);

    // layer 2
    agg_kernel<<<N, DIM>>>(h1, comp2);
    gemm_tc<<<gBlocks, 256, GEMM_SMEM>>>(Tm, Bp2, bias2, out, N, 0);
}

// round 7
// speedup vs baseline: 2.2086x; 1.1210x over previous
#include <cuda_runtime.h>
#include <cuda_bf16.h>
#include <cstdint>

#define N_NODES 50000
#define N_EDGES 1600000
#define DIM 128
#define NREL 24
#define NBASE 8
#define KTA 1024               // T width (basis part only)
#define KTOT 1152              // full K: 1024 basis + 128 root
#define BK 32
#define NKT32 (KTOT / BK)      // 36
#define NKT_T (KTA / BK)       // 32 tiles from T, rest from h

// ---------------- scratch ----------------
__device__ int   g_cnt_node[N_NODES + 1];
__device__ int   g_row_ptr [N_NODES + 1];
__device__ int   g_cursor  [N_NODES];
__device__ int   g_cnt_nr  [N_NODES * NREL];
__device__ int   g_sorted  [N_EDGES];
__device__ int   g_blk     [64];
__device__ __align__(16) float g_h0[N_NODES * DIM];
__device__ __align__(16) float g_h1[N_NODES * DIM];
__device__ __align__(16) float g_T [(size_t)N_NODES * KTA];    // 204.8 MB
__device__ __align__(16) float g_Bp1[KTOT * DIM];              // tf32-rounded [k][n]
__device__ __align__(16) float g_Bp2[KTOT * DIM];

// ---------------- helpers ----------------
__device__ __forceinline__ uint32_t smem_u32(const void* p) {
    uint32_t a;
    asm("{ .reg .u64 t; cvta.to.shared.u64 t, %1; cvt.u32.u64 %0, t; }"
        : "=r"(a) : "l"(p));
    return a;
}
__device__ __forceinline__ float tf32r(float x) {
    uint32_t u;
    asm("cvt.rna.tf32.f32 %0, %1;" : "=r"(u) : "f"(x));
    return __uint_as_float(u);
}
__device__ __forceinline__ void cp16(uint32_t dst, const void* src, int sz) {
    asm volatile("cp.async.cg.shared.global [%0], [%1], 16, %2;"
                 :: "r"(dst), "l"(src), "r"(sz) : "memory");
}
#define CP_COMMIT() asm volatile("cp.async.commit_group;" ::: "memory")
#define CP_WAIT1()  asm volatile("cp.async.wait_group 1;" ::: "memory")
#define CP_WAIT0()  asm volatile("cp.async.wait_group 0;" ::: "memory")

__device__ __forceinline__ void mma_tf32(float c[4], const uint32_t a[4],
                                         uint32_t b0, uint32_t b1) {
    asm volatile(
        "mma.sync.aligned.m16n8k8.row.col.f32.tf32.tf32.f32 "
        "{%0,%1,%2,%3}, {%4,%5,%6,%7}, {%8,%9}, {%0,%1,%2,%3};\n"
        : "+f"(c[0]), "+f"(c[1]), "+f"(c[2]), "+f"(c[3])
        : "r"(a[0]), "r"(a[1]), "r"(a[2]), "r"(a[3]), "r"(b0), "r"(b1));
}

// packed fp32x2 FMA (Blackwell FFMA2): d = a*b + d, elementwise on pairs
__device__ __forceinline__ void ffma2(unsigned long long& d,
                                      unsigned long long a,
                                      unsigned long long b) {
    asm("fma.rn.f32x2 %0, %1, %2, %0;" : "+l"(d) : "l"(a), "l"(b));
}
__device__ __forceinline__ unsigned long long pack2(float lo, float hi) {
    unsigned long long p;
    asm("mov.b64 %0, {%1, %2};" : "=l"(p) : "f"(lo), "f"(hi));
    return p;
}
__device__ __forceinline__ void unpack2(unsigned long long p, float& lo, float& hi) {
    asm("mov.b64 {%0, %1}, %2;" : "=f"(lo), "=f"(hi) : "l"(p));
}

// ---------------- graph preprocessing ----------------

__global__ void zero_nr_kernel() {
    int total = N_NODES * NREL;
    for (int i = blockIdx.x * blockDim.x + threadIdx.x; i < total;
         i += gridDim.x * blockDim.x)
        g_cnt_nr[i] = 0;
}

__global__ void hist_kernel(const int* __restrict__ e_dst,
                            const int* __restrict__ e_typ, int E) {
    for (int e = blockIdx.x * blockDim.x + threadIdx.x; e < E;
         e += gridDim.x * blockDim.x)
        atomicAdd(&g_cnt_nr[e_dst[e] * NREL + e_typ[e]], 1);
}

__global__ void csr_part1() {
    int n = blockIdx.x * 1024 + threadIdx.x;
    int v = 0;
    if (n < N_NODES) {
        const int* p = &g_cnt_nr[n * NREL];
        #pragma unroll
        for (int t = 0; t < NREL; t++) v += p[t];
        g_cnt_node[n] = v;
    }
    __shared__ int ws[32];
    int lane = threadIdx.x & 31, wid = threadIdx.x >> 5;
    int x = v;
    #pragma unroll
    for (int d = 16; d > 0; d >>= 1) x += __shfl_down_sync(0xffffffffu, x, d);
    if (lane == 0) ws[wid] = x;
    __syncthreads();
    if (wid == 0) {
        int s = ws[lane];
        #pragma unroll
        for (int d = 16; d > 0; d >>= 1) s += __shfl_down_sync(0xffffffffu, s, d);
        if (lane == 0) g_blk[blockIdx.x] = s;
    }
}

__global__ void csr_part2(int nblk) {
    if (threadIdx.x == 0) {
        int s = 0;
        for (int i = 0; i < nblk; i++) { int t = g_blk[i]; g_blk[i] = s; s += t; }
    }
}

__global__ void csr_part3() {
    __shared__ int ws[32];
    int tid = threadIdx.x, lane = tid & 31, wid = tid >> 5;
    int n = blockIdx.x * 1024 + tid;
    int v = (n < N_NODES) ? g_cnt_node[n] : 0;
    int x = v;
    #pragma unroll
    for (int d = 1; d < 32; d <<= 1) {
        int y = __shfl_up_sync(0xffffffffu, x, d);
        if (lane >= d) x += y;
    }
    if (lane == 31) ws[wid] = x;
    __syncthreads();
    if (wid == 0) {
        int s = ws[lane];
        #pragma unroll
        for (int d = 1; d < 32; d <<= 1) {
            int y = __shfl_up_sync(0xffffffffu, s, d);
            if (lane >= d) s += y;
        }
        ws[lane] = s;
    }
    __syncthreads();
    int off = (wid > 0 ? ws[wid - 1] : 0) + g_blk[blockIdx.x];
    int excl = x - v + off;
    if (n < N_NODES) { g_row_ptr[n] = excl; g_cursor[n] = excl; }
    if (n == N_NODES - 1) g_row_ptr[N_NODES] = excl + v;
}

__global__ void scatter_kernel(const int* __restrict__ e_src,
                               const int* __restrict__ e_dst,
                               const int* __restrict__ e_typ, int E) {
    for (int e = blockIdx.x * blockDim.x + threadIdx.x; e < E;
         e += gridDim.x * blockDim.x) {
        int pos = atomicAdd(&g_cursor[e_dst[e]], 1);
        g_sorted[pos] = (e_src[e] << 5) | e_typ[e];
    }
}

__global__ void embed_kernel(const int* __restrict__ x,
                             const float* __restrict__ table) {
    int n = blockIdx.x, i = threadIdx.x;
    g_h0[n * DIM + i] = table[(size_t)x[n] * DIM + i];
}

// Bp[k][n] = tf32_round(k<1024 ? bases[k][n] : root[k-1024][n])
__global__ void prep_b_kernel(const float* __restrict__ bases,
                              const float* __restrict__ root,
                              float* __restrict__ Bp) {
    int k = blockIdx.x, n = threadIdx.x;
    float v = (k < NBASE * DIM) ? bases[k * DIM + n]
                                : root[(k - NBASE * DIM) * DIM + n];
    Bp[k * DIM + n] = tf32r(v);
}

// ---------------- aggregation: 1 CTA/node, 64 lanes x 2 features ------
// Packed-f32x2 path: per edge per lane = 1 LDG.64 + 8 LDS.64 + 8 FFMA2.
__global__ void agg_kernel(const float* __restrict__ h,
                           const float* __restrict__ comp) {
    __shared__ unsigned long long s_w2[NREL * NBASE];   // (w,w) pairs
    __shared__ float s_invc[NREL];
    int n = blockIdx.x, t = threadIdx.x;   // t in [0,64)
    if (t < NREL) {
        int c = g_cnt_nr[n * NREL + t];
        s_invc[t] = 1.0f / fmaxf((float)c, 1.0f);
    }
    __syncthreads();
    for (int idx = t; idx < NREL * NBASE; idx += 64) {
        float w = comp[idx] * s_invc[idx >> 3];
        s_w2[idx] = pack2(w, w);
    }
    __syncthreads();

    unsigned long long acc[NBASE];
    #pragma unroll
    for (int b = 0; b < NBASE; b++) acc[b] = 0ull;

    const unsigned long long* h2 = (const unsigned long long*)h;  // row = 64 pairs

    int s = g_row_ptr[n], e = g_row_ptr[n + 1];
    int i = s;
    for (; i + 8 <= e; i += 8) {
        int p[8];
        unsigned long long v[8];
        #pragma unroll
        for (int u = 0; u < 8; u++) p[u] = g_sorted[i + u];
        #pragma unroll
        for (int u = 0; u < 8; u++)
            v[u] = __ldg(&h2[(size_t)(p[u] >> 5) * 64 + t]);
        #pragma unroll
        for (int u = 0; u < 8; u++) {
            const unsigned long long* wr = &s_w2[(p[u] & 31) * NBASE];
            #pragma unroll
            for (int b = 0; b < NBASE; b++) ffma2(acc[b], v[u], wr[b]);
        }
    }
    for (; i < e; i++) {
        int p = g_sorted[i];
        unsigned long long v = __ldg(&h2[(size_t)(p >> 5) * 64 + t]);
        const unsigned long long* wr = &s_w2[(p & 31) * NBASE];
        #pragma unroll
        for (int b = 0; b < NBASE; b++) ffma2(acc[b], v, wr[b]);
    }

    float* o = g_T + (size_t)n * KTA + 2 * t;
    #pragma unroll
    for (int b = 0; b < NBASE; b++) {
        float lo, hi;
        unpack2(acc[b], lo, hi);
        *(float2*)&o[b * DIM] = make_float2(tf32r(lo), tf32r(hi));
    }
}

// ---------------- tf32 mma.sync GEMM with cp.async double buffer ------
// out[M,128] = [T | h][M,1152] @ Bp[1152,128] + bias (opt relu)
// BM=128, BN=128, BK=32; 256 threads, 8 warps (4x2), warp tile 32x64.
#define AS_STRIDE 36
#define BS_STRIDE 136
#define AS_FLOATS (128 * AS_STRIDE)          // per stage
#define BS_FLOATS (BK * BS_STRIDE)
#define GEMM_SMEM ((2 * AS_FLOATS + 2 * BS_FLOATS) * 4)   // 71,680 B

__global__ __launch_bounds__(256)
void gemm_tc(const float* __restrict__ A,      // T, width KTA
             const float* __restrict__ Hin,    // h, width 128 (root chunk)
             const float* __restrict__ Bp,
             const float* __restrict__ bias,
             float* __restrict__ out, int M, int doRelu) {
    extern __shared__ __align__(16) uint32_t smbuf[];
    uint32_t* AsBase = smbuf;                   // 2 stages
    uint32_t* BsBase = smbuf + 2 * AS_FLOATS;

    int tid  = threadIdx.x;
    int lane = tid & 31;
    int wid  = tid >> 5;
    int wm = (wid >> 1) * 32;     // warp m offset
    int wn = (wid & 1) * 64;      // warp n offset
    int g  = lane >> 2;           // 0..7
    int tg = lane & 3;            // 0..3
    int m0 = blockIdx.x * 128;

    // cp.async thread mapping
    int aRow  = tid >> 1;                // 0..127
    int aCol0 = (tid & 1) * 16;          // 0 or 16 (floats)
    int bRow  = tid >> 3;                // 0..31
    int bCol0 = (tid & 7) * 16;          // 0..112 (floats)

    int aSz = (m0 + aRow < M) ? 16 : 0;  // zero-fill OOB rows
    const float* aSrcT = A   + (size_t)(m0 + aRow) * KTA + aCol0;
    const float* aSrcH = Hin + (size_t)(m0 + aRow) * DIM + aCol0;
    uint32_t aDst0 = smem_u32(&AsBase[aRow * AS_STRIDE + aCol0]);
    uint32_t bDst0 = smem_u32(&BsBase[bRow * BS_STRIDE + bCol0]);

    float acc[2][8][4];
    #pragma unroll
    for (int mt = 0; mt < 2; mt++) {
        #pragma unroll
        for (int nt = 0; nt < 8; nt++) {
            #pragma unroll
            for (int q = 0; q < 4; q++) acc[mt][nt][q] = 0.0f;
        }
    }

    // issue stage for k-tile kt into buffer s
    auto issue = [&](int s, int kt) {
        const float* as = (kt < NKT_T) ? (aSrcT + kt * BK)
                                       : (aSrcH + (kt - NKT_T) * BK);
        uint32_t ad = aDst0 + s * AS_FLOATS * 4;
        #pragma unroll
        for (int c = 0; c < 4; c++)
            cp16(ad + c * 16, as + c * 4, aSz);
        const float* bs = Bp + (size_t)(kt * BK + bRow) * DIM + bCol0;
        uint32_t bd = bDst0 + s * BS_FLOATS * 4;
        #pragma unroll
        for (int c = 0; c < 4; c++)
            cp16(bd + c * 16, bs + c * 4, 16);
        CP_COMMIT();
    };

    issue(0, 0);

    for (int kt = 0; kt < NKT32; kt++) {
        int cur = kt & 1;
        if (kt + 1 < NKT32) {
            issue((kt + 1) & 1, kt + 1);
            CP_WAIT1();
        } else {
            CP_WAIT0();
        }
        __syncthreads();

        const uint32_t* Asb = AsBase + cur * AS_FLOATS;
        const uint32_t* Bsb = BsBase + cur * BS_FLOATS;

        #pragma unroll
        for (int ks = 0; ks < BK; ks += 8) {
            uint32_t af[2][4];
            #pragma unroll
            for (int mt = 0; mt < 2; mt++) {
                int mm = wm + mt * 16 + g;
                af[mt][0] = Asb[(mm)     * AS_STRIDE + ks + tg];
                af[mt][1] = Asb[(mm + 8) * AS_STRIDE + ks + tg];
                af[mt][2] = Asb[(mm)     * AS_STRIDE + ks + tg + 4];
                af[mt][3] = Asb[(mm + 8) * AS_STRIDE + ks + tg + 4];
            }
            #pragma unroll
            for (int nt = 0; nt < 8; nt++) {
                int n0 = wn + nt * 8 + g;
                uint32_t b0 = Bsb[(ks + tg)     * BS_STRIDE + n0];
                uint32_t b1 = Bsb[(ks + tg + 4) * BS_STRIDE + n0];
                mma_tf32(acc[0][nt], af[0], b0, b1);
                mma_tf32(acc[1][nt], af[1], b0, b1);
            }
        }
        __syncthreads();
    }

    // epilogue: bias + optional relu
    #pragma unroll
    for (int mt = 0; mt < 2; mt++) {
        int r0 = m0 + wm + mt * 16 + g;
        #pragma unroll
        for (int nt = 0; nt < 8; nt++) {
            int col = wn + nt * 8 + 2 * tg;
            float bx = __ldg(&bias[col]), by = __ldg(&bias[col + 1]);
            float v0 = acc[mt][nt][0] + bx, v1 = acc[mt][nt][1] + by;
            float v2 = acc[mt][nt][2] + bx, v3 = acc[mt][nt][3] + by;
            if (doRelu) {
                v0 = fmaxf(v0, 0.f); v1 = fmaxf(v1, 0.f);
                v2 = fmaxf(v2, 0.f); v3 = fmaxf(v3, 0.f);
            }
            if (r0 < M)
                *(float2*)&out[(size_t)r0 * DIM + col] = make_float2(v0, v1);
            if (r0 + 8 < M)
                *(float2*)&out[(size_t)(r0 + 8) * DIM + col] = make_float2(v2, v3);
        }
    }
}

// ---------------- launcher ----------------
extern "C" void kernel_launch(void* const* d_in, const int* in_sizes, int n_in,
                              void* d_out, int out_size) {
    const int*   x      = (const int*)  d_in[0];
    const int*   eidx   = (const int*)  d_in[1];
    const int*   etyp   = (const int*)  d_in[2];
    const float* table  = (const float*)d_in[3];
    const float* comp1  = (const float*)d_in[4];
    const float* bases1 = (const float*)d_in[5];
    const float* root1  = (const float*)d_in[6];
    const float* bias1  = (const float*)d_in[7];
    const float* comp2  = (const float*)d_in[8];
    const float* bases2 = (const float*)d_in[9];
    const float* root2  = (const float*)d_in[10];
    const float* bias2  = (const float*)d_in[11];

    const int E = in_sizes[2];
    const int N = in_sizes[0];
    const int* e_src = eidx;
    const int* e_dst = eidx + E;
    float* out = (float*)d_out;

    float *h0, *h1, *Tm, *Bp1, *Bp2;
    cudaGetSymbolAddress((void**)&h0,  g_h0);
    cudaGetSymbolAddress((void**)&h1,  g_h1);
    cudaGetSymbolAddress((void**)&Tm,  g_T);
    cudaGetSymbolAddress((void**)&Bp1, g_Bp1);
    cudaGetSymbolAddress((void**)&Bp2, g_Bp2);

    cudaFuncSetAttribute(gemm_tc,
                         cudaFuncAttributeMaxDynamicSharedMemorySize, GEMM_SMEM);

    int eBlocks = (E + 255) / 256;
    int zBlocks = (N * NREL + 255) / 256;
    int sBlocks = (N + 1023) / 1024;
    int gBlocks = (N + 127) / 128;

    // CSR build
    zero_nr_kernel<<<zBlocks, 256>>>();
    hist_kernel<<<eBlocks, 256>>>(e_dst, etyp, E);
    csr_part1<<<sBlocks, 1024>>>();
    csr_part2<<<1, 32>>>(sBlocks);
    csr_part3<<<sBlocks, 1024>>>();
    scatter_kernel<<<eBlocks, 256>>>(e_src, e_dst, etyp, E);

    // embedding + weight prep
    embed_kernel<<<N, DIM>>>(x, table);
    prep_b_kernel<<<KTOT, DIM>>>(bases1, root1, Bp1);
    prep_b_kernel<<<KTOT, DIM>>>(bases2, root2, Bp2);

    // layer 1
    agg_kernel<<<N, 64>>>(h0, comp1);
    gemm_tc<<<gBlocks, 256, GEMM_SMEM>>>(Tm, h0, Bp1, bias1, h1, N, 1);

    // layer 2
    agg_kernel<<<N, 64>>>(h1, comp2);
    gemm_tc<<<gBlocks, 256, GEMM_SMEM>>>(Tm, h1, Bp2, bias2, out, N, 0);
}